// round 15
// baseline (speedup 1.0000x reference)
#include <cuda_runtime.h>
#include <math.h>
#include <stdint.h>

// ---------------- problem constants ----------------
#define Bs      8
#define HEAD    512
#define FMP     40
#define NPOS    1600      // FMP*FMP
#define NCLS    20
#define CONF_T  0.001f
#define NMS_T   0.6f

// output layout (float32): bboxes | best | cls_inds | keep
#define OFF_BEST  (Bs*NPOS*4)          // 51200
#define OFF_CLS   (OFF_BEST + Bs*NPOS) // 64000
#define OFF_KEEP  (OFF_CLS  + Bs*NPOS) // 76800

#define WPER   (512L*4608L)            // fp32 weights per conv layer
#define ACT_N  (Bs * HEAD * NPOS)      // 6,553,600 activations

// ---------------- Winograd F(4x4,3x3) dims ----------------
#define XI     36                      // 6x6 transformed components
#define NT1    10                      // tiles per axis
#define NTILE  100                     // tiles per image
#define TPOS   (Bs*NTILE)              // 800 tile-positions
#define U_L    (36L*4*512*128)         // U floats per layer = 9,437,184
#define VM_N   (36L*512*TPOS)          // V/M floats = 14,745,600

// ---------------- scratch (device globals, no runtime alloc) ----------------
__device__ float g_bufB[ACT_N];
__device__ float g_bufC[ACT_N];
__device__ float g_best[Bs * NPOS];
__device__ int   g_clsi[Bs * NPOS];
__device__ float g_U[6 * U_L];         // transformed weights, 226 MB
__device__ float g_Vx[VM_N];           // V of input x (shared by both chains)
__device__ float g_V0[VM_N];           // reg-chain V
__device__ float g_M0[VM_N];           // reg-chain M
__device__ float g_V1[VM_N];           // cls-chain V
__device__ float g_M1[VM_N];           // cls-chain M

// ---------------- packed f32x2 / cp.async helpers ----------------
__device__ __forceinline__ void fma2(float2 &d, float2 a, float2 b) {
    asm("fma.rn.f32x2 %0, %1, %2, %0;"
        : "+l"(reinterpret_cast<unsigned long long&>(d))
        : "l"(reinterpret_cast<unsigned long long&>(a)),
          "l"(reinterpret_cast<unsigned long long&>(b)));
}
__device__ __forceinline__ uint32_t smem_u32(const void* p) {
    uint32_t a;
    asm("{ .reg .u64 t; cvta.to.shared.u64 t, %1; cvt.u32.u64 %0, t; }" : "=r"(a) : "l"(p));
    return a;
}
__device__ __forceinline__ void cp_async16(uint32_t dst, const void* src) {
    asm volatile("cp.async.cg.shared.global [%0], [%1], 16;" :: "r"(dst), "l"(src));
}
__device__ __forceinline__ void cp_commit() { asm volatile("cp.async.commit_group;"); }
__device__ __forceinline__ void cp_wait0()  { asm volatile("cp.async.wait_group 0;" ::: "memory"); }

// ---- F(4,3) 1D transform helpers ----
__device__ __forceinline__ void gcomb(float g0, float g1, float g2, float* o) {
    o[0] = 0.25f * g0;
    o[1] = (-g0 - g1 - g2) * (1.f / 6.f);
    o[2] = (-g0 + g1 - g2) * (1.f / 6.f);
    o[3] = g0 * (1.f / 24.f) + g1 * (1.f / 12.f) + g2 * (1.f / 6.f);
    o[4] = g0 * (1.f / 24.f) - g1 * (1.f / 12.f) + g2 * (1.f / 6.f);
    o[5] = g2;
}
__device__ __forceinline__ void btcomb(const float* a, float* o) {
    o[0] = 4.f * a[0] - 5.f * a[2] + a[4];
    o[1] = -4.f * a[1] - 4.f * a[2] + a[3] + a[4];
    o[2] =  4.f * a[1] - 4.f * a[2] - a[3] + a[4];
    o[3] = -2.f * a[1] - a[2] + 2.f * a[3] + a[4];
    o[4] =  2.f * a[1] - a[2] - 2.f * a[3] + a[4];
    o[5] =  4.f * a[1] - 5.f * a[3] + a[5];
}
__device__ __forceinline__ void atcomb(const float* m, float* y) {
    y[0] = m[0] + m[1] + m[2] + m[3] + m[4];
    y[1] = m[1] - m[2] + 2.f * (m[3] - m[4]);
    y[2] = m[1] + m[2] + 4.f * (m[3] + m[4]);
    y[3] = m[1] - m[2] + 8.f * (m[3] - m[4]) + m[5];
}

// ---------------- one-shot weight transform: U = G g G^T ----------------
// U layout: [l(6)][xi(36)][ocg(4)][ic(512)][oc_in(128)]
__global__ void __launch_bounds__(256)
wino_wt_k(const float* __restrict__ cls_w, const float* __restrict__ reg_w,
          float* __restrict__ U)
{
    long i = (long)blockIdx.x * 256 + threadIdx.x;
    if (i >= 6L * 512 * 512) return;
    int  oc = (int)(i & 511);
    long r  = i >> 9;
    int  ic = (int)(r & 511);
    int  l  = (int)(r >> 9);
    const float* src = (l < 2) ? (cls_w + (long)l * WPER)
                               : (reg_w + (long)(l - 2) * WPER);
    const float* g = src + (long)oc * 4608 + ic * 9;

    float t[6][3];
    {
        float c0[6], c1[6], c2[6];
        gcomb(g[0], g[3], g[6], c0);
        gcomb(g[1], g[4], g[7], c1);
        gcomb(g[2], g[5], g[8], c2);
#pragma unroll
        for (int rr = 0; rr < 6; rr++) { t[rr][0] = c0[rr]; t[rr][1] = c1[rr]; t[rr][2] = c2[rr]; }
    }
    long base = (long)l * U_L + ((long)(oc >> 7) * 512 + ic) * 128 + (oc & 127);
#pragma unroll
    for (int rr = 0; rr < 6; rr++) {
        float u[6];
        gcomb(t[rr][0], t[rr][1], t[rr][2], u);
#pragma unroll
        for (int cc = 0; cc < 6; cc++)
            U[base + (long)(rr * 6 + cc) * (4L * 512 * 128)] = u[cc];
    }
}

// ---------------- input transform: V = B^T d B ----------------
// V layout: [xi(36)][ic(512)][t(800)], t = b*100 + ty*10 + tx
__global__ void __launch_bounds__(256)
wino_in_k(const float* __restrict__ act, float* __restrict__ V)
{
    long i = (long)blockIdx.x * 256 + threadIdx.x;
    if (i >= 512L * TPOS) return;
    int t  = (int)(i % TPOS);
    int ic = (int)(i / TPOS);
    int b  = t / NTILE;
    int tt = t - b * NTILE;
    int ty = tt / NT1;
    int tx = tt - ty * NT1;
    const float* ab = act + ((long)b * HEAD + ic) * NPOS;

    float d[6][6];
#pragma unroll
    for (int r = 0; r < 6; r++) {
        int y = 4 * ty - 1 + r;
#pragma unroll
        for (int c = 0; c < 6; c++) {
            int x = 4 * tx - 1 + c;
            d[r][c] = ((unsigned)y < 40u && (unsigned)x < 40u) ? ab[y * 40 + x] : 0.f;
        }
    }
    float z[6][6];
    {
        float col[6], o[6];
#pragma unroll
        for (int c = 0; c < 6; c++) {
#pragma unroll
            for (int r = 0; r < 6; r++) col[r] = d[r][c];
            btcomb(col, o);
#pragma unroll
            for (int r = 0; r < 6; r++) z[r][c] = o[r];
        }
    }
#pragma unroll
    for (int r = 0; r < 6; r++) {
        float o[6];
        btcomb(z[r], o);
#pragma unroll
        for (int c = 0; c < 6; c++)
            V[((long)(r * 6 + c) * 512 + ic) * TPOS + t] = o[c];
    }
}

// ---------------- batched GEMM: M[xi][oc][t] = sum_ic U[xi][oc][ic] * V[xi][ic][t] ----
// grid (10 pos-blocks, 4 ocg, 36 xi), 128 threads, ic-step 16 (32 k-steps).
// thread: og = tid>>3 -> 8 oc (og*8..+7) as 4 f32x2 pairs; ps = tid&7 -> 10 pos.
__global__ void __launch_bounds__(128, 4)
wino_gemm_k(const float* __restrict__ V, const float* __restrict__ Ul,
            float* __restrict__ M)
{
    __shared__ float  s_u[2][16 * 128];    // 2 x 8192 B
    __shared__ float2 s_v[2][16 * 80];     // 2 x 10240 B (duplicated pairs)

    const int tid  = threadIdx.x;
    const int og   = tid >> 3;
    const int ps   = tid & 7;
    const int pos0 = blockIdx.x * 80;
    const int ocg  = blockIdx.y;
    const int xi   = blockIdx.z;

    float2 acc[4][10];
#pragma unroll
    for (int j = 0; j < 4; j++)
#pragma unroll
        for (int p = 0; p < 10; p++) acc[j][p] = make_float2(0.f, 0.f);

    const float* ub = Ul + ((long)xi * 4 + ocg) * (512L * 128);
    const float* vb = V + (long)xi * 512 * TPOS + pos0;

    auto stage_u = [&](int buf, int s) {
        uint32_t ud = smem_u32(&s_u[buf][0]);
        const float4* us = (const float4*)(ub + (long)s * 2048);
#pragma unroll
        for (int k = 0; k < 4; k++)
            cp_async16(ud + (tid + 128 * k) * 16, us + tid + 128 * k);
    };
    auto load_v = [&](int s, float* rv) {
#pragma unroll
        for (int k = 0; k < 10; k++) {
            int idx = tid + 128 * k;
            int ici = idx / 80;
            int p   = idx - ici * 80;
            rv[k] = vb[(long)(s * 16 + ici) * TPOS + p];
        }
    };
    auto store_v = [&](int buf, const float* rv) {
#pragma unroll
        for (int k = 0; k < 10; k++) {
            int idx = tid + 128 * k;
            s_v[buf][idx] = make_float2(rv[k], rv[k]);
        }
    };

    // prologue
    {
        float rv[10];
        stage_u(0, 0);
        cp_commit();
        load_v(0, rv);
        store_v(0, rv);
        cp_wait0();
    }
    __syncthreads();

    for (int s = 0; s < 32; s++) {
        const int cur = s & 1;
        float rv[10];
        if (s < 31) {
            stage_u(1 - cur, s + 1);
            cp_commit();
            load_v(s + 1, rv);
        }

#pragma unroll 8
        for (int i = 0; i < 16; i++) {
            const float4* vp = (const float4*)(&s_v[cur][i * 80 + ps * 10]);
            float2 iv[10];
#pragma unroll
            for (int q = 0; q < 5; q++) {
                float4 f = vp[q];
                iv[2 * q]     = make_float2(f.x, f.y);
                iv[2 * q + 1] = make_float2(f.z, f.w);
            }
            const float4* up = (const float4*)(&s_u[cur][i * 128 + og * 8]);
            float4 w0 = up[0], w1 = up[1];
            float2 wp0 = make_float2(w0.x, w0.y);
            float2 wp1 = make_float2(w0.z, w0.w);
            float2 wp2 = make_float2(w1.x, w1.y);
            float2 wp3 = make_float2(w1.z, w1.w);
#pragma unroll
            for (int p = 0; p < 10; p++) {
                fma2(acc[0][p], wp0, iv[p]);
                fma2(acc[1][p], wp1, iv[p]);
                fma2(acc[2][p], wp2, iv[p]);
                fma2(acc[3][p], wp3, iv[p]);
            }
        }

        if (s < 31) {
            store_v(1 - cur, rv);
            cp_wait0();
        }
        __syncthreads();
    }

#pragma unroll
    for (int j = 0; j < 4; j++) {
        int oc0 = ocg * 128 + og * 8 + 2 * j;
        float* m0 = M + ((long)xi * 512 + oc0) * TPOS + pos0 + ps * 10;
        float* m1 = m0 + TPOS;
#pragma unroll
        for (int p = 0; p < 10; p++) {
            m0[p] = acc[j][p].x;
            m1[p] = acc[j][p].y;
        }
    }
}

// ---------------- output transform: Y = A^T m A + bias + leaky ----------------
__global__ void __launch_bounds__(256)
wino_out_k(const float* __restrict__ M, const float* __restrict__ bias,
           float* __restrict__ act)
{
    long i = (long)blockIdx.x * 256 + threadIdx.x;
    if (i >= 512L * TPOS) return;
    int t  = (int)(i % TPOS);
    int oc = (int)(i / TPOS);
    int b  = t / NTILE;
    int tt = t - b * NTILE;
    int ty = tt / NT1;
    int tx = tt - ty * NT1;

    float m[6][6];
#pragma unroll
    for (int xi = 0; xi < XI; xi++)
        m[xi / 6][xi % 6] = M[((long)xi * 512 + oc) * TPOS + t];

    float s[4][6];
    {
        float col[6], o[4];
#pragma unroll
        for (int c = 0; c < 6; c++) {
#pragma unroll
            for (int r = 0; r < 6; r++) col[r] = m[r][c];
            atcomb(col, o);
#pragma unroll
            for (int r = 0; r < 4; r++) s[r][c] = o[r];
        }
    }

    float bv = bias[oc];
    float* ob = act + ((long)b * HEAD + oc) * NPOS + (4 * ty) * 40 + 4 * tx;
#pragma unroll
    for (int r = 0; r < 4; r++) {
        float y[4];
        atcomb(s[r], y);
#pragma unroll
        for (int c = 0; c < 4; c++) {
            float v = y[c] + bv;
            ob[r * 40 + c] = v > 0.f ? v : 0.1f * v;
        }
    }
}

// ---------------- 1x1 heads + decode, K-split x2 ----------------
__global__ void __launch_bounds__(128)
heads_decode_k(const float* __restrict__ cf, const float* __restrict__ rf,
               const float* __restrict__ obj_w, const float* __restrict__ obj_b,
               const float* __restrict__ clsp_w, const float* __restrict__ clsp_b,
               const float* __restrict__ regp_w, const float* __restrict__ regp_b,
               float* __restrict__ out, float* __restrict__ best_s, int* __restrict__ cls_s)
{
    const int b = blockIdx.y;
    const int p = threadIdx.x & 63;
    const int h = threadIdx.x >> 6;
    const int n = blockIdx.x * 64 + p;
    const int ch0 = h * 256;

    const float* cfb = cf + ((long)b * HEAD + ch0) * NPOS + n;
    const float* rfb = rf + ((long)b * HEAD + ch0) * NPOS + n;

    float accC[NCLS];
    float accR[4];
    float accO = 0.f;
#pragma unroll
    for (int c = 0; c < NCLS; c++) accC[c] = 0.f;
#pragma unroll
    for (int k = 0; k < 4; k++) accR[k] = 0.f;

#pragma unroll 4
    for (int ch = 0; ch < 256; ch++) {
        float cv = cfb[(long)ch * NPOS];
        float rv = rfb[(long)ch * NPOS];
        accO = fmaf(rv, __ldg(&obj_w[ch0 + ch]), accO);
#pragma unroll
        for (int k = 0; k < 4; k++)
            accR[k] = fmaf(rv, __ldg(&regp_w[k * HEAD + ch0 + ch]), accR[k]);
#pragma unroll
        for (int c = 0; c < NCLS; c++)
            accC[c] = fmaf(cv, __ldg(&clsp_w[c * HEAD + ch0 + ch]), accC[c]);
    }

    __shared__ float sred[64][25];
    if (h == 1) {
#pragma unroll
        for (int c = 0; c < NCLS; c++) sred[p][c] = accC[c];
#pragma unroll
        for (int k = 0; k < 4; k++) sred[p][NCLS + k] = accR[k];
        sred[p][24] = accO;
    }
    __syncthreads();
    if (h != 0) return;

#pragma unroll
    for (int c = 0; c < NCLS; c++) accC[c] += sred[p][c];
#pragma unroll
    for (int k = 0; k < 4; k++) accR[k] += sred[p][NCLS + k];
    accO += sred[p][24];

    accO += obj_b[0];
#pragma unroll
    for (int k = 0; k < 4; k++) accR[k] += regp_b[k];
#pragma unroll
    for (int c = 0; c < NCLS; c++) accC[c] += clsp_b[c];

    float mx = accC[0];
    int am = 0;
#pragma unroll
    for (int c = 1; c < NCLS; c++)
        if (accC[c] > mx) { mx = accC[c]; am = c; }
    float s = 0.f;
#pragma unroll
    for (int c = 0; c < NCLS; c++) s += expf(accC[c] - mx);
    float sig_o = 1.f / (1.f + expf(-accO));
    float best  = sig_o / s;

    float gx = (float)(n % FMP);
    float gy = (float)(n / FMP);
    float cx = 1.f / (1.f + expf(-accR[0])) + gx;
    float cy = 1.f / (1.f + expf(-accR[1])) + gy;
    float ww = expf(accR[2]);
    float hh = expf(accR[3]);

    float bx1 = (cx - ww * 0.5f) * 32.f / 1280.f;
    float by1 = (cy - hh * 0.5f) * 32.f / 1280.f;
    float bx2 = (cx + ww * 0.5f) * 32.f / 1280.f;
    float by2 = (cy + hh * 0.5f) * 32.f / 1280.f;
    bx1 = fminf(fmaxf(bx1, 0.f), 1.f);
    by1 = fminf(fmaxf(by1, 0.f), 1.f);
    bx2 = fminf(fmaxf(bx2, 0.f), 1.f);
    by2 = fminf(fmaxf(by2, 0.f), 1.f);

    const int gi = b * NPOS + n;
    out[gi * 4 + 0] = bx1;
    out[gi * 4 + 1] = by1;
    out[gi * 4 + 2] = bx2;
    out[gi * 4 + 3] = by2;
    out[OFF_BEST + gi] = best;
    out[OFF_CLS  + gi] = (float)am;
    out[OFF_KEEP + gi] = 0.f;
    best_s[gi] = best;
    cls_s[gi]  = am;
}

// ---------------- per-(batch, class) greedy NMS ----------------
__global__ void __launch_bounds__(256)
nms_k(const float* __restrict__ out_boxes,
      float* __restrict__ out_keep,
      const float* __restrict__ best_s, const int* __restrict__ cls_s)
{
    const int b = blockIdx.x / NCLS;
    const int c = blockIdx.x % NCLS;
    const int tid = threadIdx.x;

    __shared__ float sx1[NPOS], sy1[NPOS], sx2[NPOS], sy2[NPOS];
    __shared__ float ssc[NPOS];
    __shared__ int   sidx[NPOS];
    __shared__ unsigned short ord[NPOS];
    __shared__ unsigned char aliveR[NPOS];
    __shared__ int scnt;

    if (tid == 0) scnt = 0;
    __syncthreads();

    for (int n = tid; n < NPOS; n += 256) {
        int gi = b * NPOS + n;
        if (cls_s[gi] == c && best_s[gi] >= CONF_T) {
            int p = atomicAdd(&scnt, 1);
            sidx[p] = n;
            ssc[p]  = best_s[gi];
            const float* bp = out_boxes + (long)gi * 4;
            sx1[p] = bp[0]; sy1[p] = bp[1]; sx2[p] = bp[2]; sy2[p] = bp[3];
        }
    }
    __syncthreads();
    const int cnt = scnt;

    for (int i = tid; i < cnt; i += 256) {
        float si = ssc[i];
        int   ii = sidx[i];
        int rnk = 0;
        for (int j = 0; j < cnt; j++) {
            float sj = ssc[j];
            if (sj > si || (sj == si && sidx[j] < ii)) rnk++;
        }
        ord[rnk] = (unsigned short)i;
        aliveR[rnk] = 1;
    }
    __syncthreads();

    for (int r = 0; r < cnt; r++) {
        __syncthreads();
        if (!aliveR[r]) continue;
        int li = ord[r];
        float bx1 = sx1[li], by1 = sy1[li], bx2 = sx2[li], by2 = sy2[li];
        float ai = (bx2 - bx1) * (by2 - by1);
        for (int rr = r + 1 + tid; rr < cnt; rr += 256) {
            if (!aliveR[rr]) continue;
            int lj = ord[rr];
            float jx1 = sx1[lj], jy1 = sy1[lj], jx2 = sx2[lj], jy2 = sy2[lj];
            float xx1 = fmaxf(bx1, jx1);
            float yy1 = fmaxf(by1, jy1);
            float xx2 = fminf(bx2, jx2);
            float yy2 = fminf(by2, jy2);
            float w2 = fmaxf(1e-28f, xx2 - xx1);
            float h2 = fmaxf(1e-28f, yy2 - yy1);
            float inter = w2 * h2;
            float aj = (jx2 - jx1) * (jy2 - jy1);
            float iou = inter / (ai + aj - inter + 1e-14f);
            if (iou > NMS_T) aliveR[rr] = 0;
        }
    }
    __syncthreads();

    for (int r = tid; r < cnt; r += 256)
        if (aliveR[r])
            out_keep[b * NPOS + sidx[ord[r]]] = 1.f;
}

// ---------------- launch ----------------
extern "C" void kernel_launch(void* const* d_in, const int* in_sizes, int n_in,
                              void* d_out, int out_size)
{
    const float* x      = (const float*)d_in[0];
    const float* cls_w  = (const float*)d_in[1];
    const float* cls_b  = (const float*)d_in[2];
    const float* reg_w  = (const float*)d_in[3];
    const float* reg_b  = (const float*)d_in[4];
    const float* obj_w  = (const float*)d_in[5];
    const float* obj_b  = (const float*)d_in[6];
    const float* clsp_w = (const float*)d_in[7];
    const float* clsp_b = (const float*)d_in[8];
    const float* regp_w = (const float*)d_in[9];
    const float* regp_b = (const float*)d_in[10];
    float* out = (float*)d_out;

    void *pB, *pC, *pBest, *pCls, *pU, *pVx, *pV0, *pM0, *pV1, *pM1;
    cudaGetSymbolAddress(&pB, g_bufB);
    cudaGetSymbolAddress(&pC, g_bufC);
    cudaGetSymbolAddress(&pBest, g_best);
    cudaGetSymbolAddress(&pCls, g_clsi);
    cudaGetSymbolAddress(&pU, g_U);
    cudaGetSymbolAddress(&pVx, g_Vx);
    cudaGetSymbolAddress(&pV0, g_V0);
    cudaGetSymbolAddress(&pM0, g_M0);
    cudaGetSymbolAddress(&pV1, g_V1);
    cudaGetSymbolAddress(&pM1, g_M1);
    float* bufB = (float*)pB;
    float* bufC = (float*)pC;
    float* bestp = (float*)pBest;
    int*   clsp  = (int*)pCls;
    float* U     = (float*)pU;
    float* Vx    = (float*)pVx;
    float* V0    = (float*)pV0;
    float* M0    = (float*)pM0;
    float* V1    = (float*)pV1;
    float* M1    = (float*)pM1;

    static cudaStream_t s2 = 0;
    static cudaEvent_t  evFork = 0, evCls = 0;
    if (!s2) {
        cudaStreamCreateWithFlags(&s2, cudaStreamNonBlocking);
        cudaEventCreateWithFlags(&evFork, cudaEventDisableTiming);
        cudaEventCreateWithFlags(&evCls, cudaEventDisableTiming);
    }

    // one-shot Winograd weight transform
    {
        long total = 6L * 512 * 512;
        int  grid  = (int)((total + 255) / 256);
        wino_wt_k<<<grid, 256>>>(cls_w, reg_w, U);
    }

    const int TGRID = (int)((512L * TPOS + 255) / 256);   // 1600
    dim3 ggrid(TPOS / 80, 4, XI);                          // (10, 4, 36)

    auto conv = [&](const float* Vsrc, int l, float* M, cudaStream_t st) {
        wino_gemm_k<<<ggrid, 128, 0, st>>>(Vsrc, U + (long)l * U_L, M);
    };

    // shared input transform of x (pre-fork)
    wino_in_k<<<TGRID, 256>>>(x, Vx);

    // fork: cls chain on s2, reg chain on default stream
    cudaEventRecord(evFork, 0);
    cudaStreamWaitEvent(s2, evFork, 0);

    // cls branch (s2): Vx -> M1 -> (out->in) -> M1 -> bufB
    conv(Vx, 0, M1, s2);
    wino_out_k<<<TGRID, 256, 0, s2>>>(M1, cls_b, bufB);     // bufB as temp act
    wino_in_k<<<TGRID, 256, 0, s2>>>(bufB, V1);
    conv(V1, 1, M1, s2);
    wino_out_k<<<TGRID, 256, 0, s2>>>(M1, cls_b + HEAD, bufB);
    cudaEventRecord(evCls, s2);

    // reg branch (default): Vx -> M0 -> ... -> bufC
    conv(Vx, 2, M0, 0);
    wino_out_k<<<TGRID, 256>>>(M0, reg_b, bufC);            // bufC as temp act
    wino_in_k<<<TGRID, 256>>>(bufC, V0);
    conv(V0, 3, M0, 0);
    wino_out_k<<<TGRID, 256>>>(M0, reg_b + HEAD, bufC);
    wino_in_k<<<TGRID, 256>>>(bufC, V0);
    conv(V0, 4, M0, 0);
    wino_out_k<<<TGRID, 256>>>(M0, reg_b + 2 * HEAD, bufC);
    wino_in_k<<<TGRID, 256>>>(bufC, V0);
    conv(V0, 5, M0, 0);
    wino_out_k<<<TGRID, 256>>>(M0, reg_b + 3 * HEAD, bufC);

    // join: heads needs both chains
    cudaStreamWaitEvent(0, evCls, 0);

    heads_decode_k<<<dim3(25, Bs), 128>>>(bufB, bufC,
                                          obj_w, obj_b, clsp_w, clsp_b,
                                          regp_w, regp_b,
                                          out, bestp, clsp);

    nms_k<<<Bs * NCLS, 256>>>(out, out + OFF_KEEP, bestp, clsp);
}

// round 16
// speedup vs baseline: 1.0773x; 1.0773x over previous
#include <cuda_runtime.h>
#include <math.h>
#include <stdint.h>

// ---------------- problem constants ----------------
#define Bs      8
#define HEAD    512
#define FMP     40
#define NPOS    1600      // FMP*FMP
#define NCLS    20
#define CONF_T  0.001f
#define NMS_T   0.6f

// output layout (float32): bboxes | best | cls_inds | keep
#define OFF_BEST  (Bs*NPOS*4)          // 51200
#define OFF_CLS   (OFF_BEST + Bs*NPOS) // 64000
#define OFF_KEEP  (OFF_CLS  + Bs*NPOS) // 76800

#define WPER   (512L*4608L)            // fp32 weights per conv layer
#define ACT_N  (Bs * HEAD * NPOS)      // 6,553,600 activations

// ---------------- Winograd F(4x4,3x3) dims ----------------
#define XI     36                      // 6x6 transformed components
#define NT1    10                      // tiles per axis
#define NTILE  100                     // tiles per image
#define TPOS   (Bs*NTILE)              // 800 tile-positions
#define U_L    (36L*4*512*128)         // U floats per layer = 9,437,184
#define VM_N   (36L*512*TPOS)          // V/M floats = 14,745,600

// ---------------- scratch (device globals, no runtime alloc) ----------------
__device__ float g_bufB[ACT_N];
__device__ float g_bufC[ACT_N];
__device__ float g_best[Bs * NPOS];
__device__ float g_cprob[Bs * NPOS];
__device__ int   g_clsi[Bs * NPOS];
__device__ float g_U[6 * U_L];         // transformed weights, 226 MB
__device__ float g_Vx[VM_N];           // V of input x (shared by both chains)
__device__ float g_V0[VM_N];           // reg-chain V
__device__ float g_M0[VM_N];           // reg-chain M
__device__ float g_V1[VM_N];           // cls-chain V
__device__ float g_M1[VM_N];           // cls-chain M

// ---------------- packed f32x2 / cp.async helpers ----------------
__device__ __forceinline__ void fma2(float2 &d, float2 a, float2 b) {
    asm("fma.rn.f32x2 %0, %1, %2, %0;"
        : "+l"(reinterpret_cast<unsigned long long&>(d))
        : "l"(reinterpret_cast<unsigned long long&>(a)),
          "l"(reinterpret_cast<unsigned long long&>(b)));
}
__device__ __forceinline__ uint32_t smem_u32(const void* p) {
    uint32_t a;
    asm("{ .reg .u64 t; cvta.to.shared.u64 t, %1; cvt.u32.u64 %0, t; }" : "=r"(a) : "l"(p));
    return a;
}
__device__ __forceinline__ void cp_async16(uint32_t dst, const void* src) {
    asm volatile("cp.async.cg.shared.global [%0], [%1], 16;" :: "r"(dst), "l"(src));
}
__device__ __forceinline__ void cp_commit() { asm volatile("cp.async.commit_group;"); }
__device__ __forceinline__ void cp_wait0()  { asm volatile("cp.async.wait_group 0;" ::: "memory"); }

// ---- F(4,3) 1D transform helpers ----
__device__ __forceinline__ void gcomb(float g0, float g1, float g2, float* o) {
    o[0] = 0.25f * g0;
    o[1] = (-g0 - g1 - g2) * (1.f / 6.f);
    o[2] = (-g0 + g1 - g2) * (1.f / 6.f);
    o[3] = g0 * (1.f / 24.f) + g1 * (1.f / 12.f) + g2 * (1.f / 6.f);
    o[4] = g0 * (1.f / 24.f) - g1 * (1.f / 12.f) + g2 * (1.f / 6.f);
    o[5] = g2;
}
__device__ __forceinline__ void btcomb(const float* a, float* o) {
    o[0] = 4.f * a[0] - 5.f * a[2] + a[4];
    o[1] = -4.f * a[1] - 4.f * a[2] + a[3] + a[4];
    o[2] =  4.f * a[1] - 4.f * a[2] - a[3] + a[4];
    o[3] = -2.f * a[1] - a[2] + 2.f * a[3] + a[4];
    o[4] =  2.f * a[1] - a[2] - 2.f * a[3] + a[4];
    o[5] =  4.f * a[1] - 5.f * a[3] + a[5];
}
__device__ __forceinline__ void atcomb(const float* m, float* y) {
    y[0] = m[0] + m[1] + m[2] + m[3] + m[4];
    y[1] = m[1] - m[2] + 2.f * (m[3] - m[4]);
    y[2] = m[1] + m[2] + 4.f * (m[3] + m[4]);
    y[3] = m[1] - m[2] + 8.f * (m[3] - m[4]) + m[5];
}

// ---------------- one-shot weight transform: U = G g G^T ----------------
// U layout: [l(6)][xi(36)][ocg(4)][ic(512)][oc_in(128)]
__global__ void __launch_bounds__(256)
wino_wt_k(const float* __restrict__ cls_w, const float* __restrict__ reg_w,
          float* __restrict__ U)
{
    long i = (long)blockIdx.x * 256 + threadIdx.x;
    if (i >= 6L * 512 * 512) return;
    int  oc = (int)(i & 511);
    long r  = i >> 9;
    int  ic = (int)(r & 511);
    int  l  = (int)(r >> 9);
    const float* src = (l < 2) ? (cls_w + (long)l * WPER)
                               : (reg_w + (long)(l - 2) * WPER);
    const float* g = src + (long)oc * 4608 + ic * 9;

    float t[6][3];
    {
        float c0[6], c1[6], c2[6];
        gcomb(g[0], g[3], g[6], c0);
        gcomb(g[1], g[4], g[7], c1);
        gcomb(g[2], g[5], g[8], c2);
#pragma unroll
        for (int rr = 0; rr < 6; rr++) { t[rr][0] = c0[rr]; t[rr][1] = c1[rr]; t[rr][2] = c2[rr]; }
    }
    long base = (long)l * U_L + ((long)(oc >> 7) * 512 + ic) * 128 + (oc & 127);
#pragma unroll
    for (int rr = 0; rr < 6; rr++) {
        float u[6];
        gcomb(t[rr][0], t[rr][1], t[rr][2], u);
#pragma unroll
        for (int cc = 0; cc < 6; cc++)
            U[base + (long)(rr * 6 + cc) * (4L * 512 * 128)] = u[cc];
    }
}

// ---------------- input transform: V = B^T d B ----------------
// V layout: [xi(36)][ic(512)][t(800)], t = b*100 + ty*10 + tx
__global__ void __launch_bounds__(256)
wino_in_k(const float* __restrict__ act, float* __restrict__ V)
{
    long i = (long)blockIdx.x * 256 + threadIdx.x;
    if (i >= 512L * TPOS) return;
    int t  = (int)(i % TPOS);
    int ic = (int)(i / TPOS);
    int b  = t / NTILE;
    int tt = t - b * NTILE;
    int ty = tt / NT1;
    int tx = tt - ty * NT1;
    const float* ab = act + ((long)b * HEAD + ic) * NPOS;

    float d[6][6];
#pragma unroll
    for (int r = 0; r < 6; r++) {
        int y = 4 * ty - 1 + r;
#pragma unroll
        for (int c = 0; c < 6; c++) {
            int x = 4 * tx - 1 + c;
            d[r][c] = ((unsigned)y < 40u && (unsigned)x < 40u) ? ab[y * 40 + x] : 0.f;
        }
    }
    float z[6][6];
    {
        float col[6], o[6];
#pragma unroll
        for (int c = 0; c < 6; c++) {
#pragma unroll
            for (int r = 0; r < 6; r++) col[r] = d[r][c];
            btcomb(col, o);
#pragma unroll
            for (int r = 0; r < 6; r++) z[r][c] = o[r];
        }
    }
#pragma unroll
    for (int r = 0; r < 6; r++) {
        float o[6];
        btcomb(z[r], o);
#pragma unroll
        for (int c = 0; c < 6; c++)
            V[((long)(r * 6 + c) * 512 + ic) * TPOS + t] = o[c];
    }
}

// ---------------- batched GEMM (R14 best version: ic-step 8, 64 steps) ----------------
// M[xi][oc][t] = sum_ic U[xi][oc][ic] * V[xi][ic][t]
// grid (10 pos-blocks, 4 ocg, 36 xi), 128 threads.
__global__ void __launch_bounds__(128, 4)
wino_gemm_k(const float* __restrict__ V, const float* __restrict__ Ul,
            float* __restrict__ M)
{
    __shared__ float  s_u[2][8 * 128];     // 2 x 4096 B
    __shared__ float2 s_v[2][8 * 80];      // 2 x 5120 B (duplicated pairs)

    const int tid  = threadIdx.x;
    const int og   = tid >> 3;
    const int ps   = tid & 7;
    const int pos0 = blockIdx.x * 80;
    const int ocg  = blockIdx.y;
    const int xi   = blockIdx.z;

    float2 acc[4][10];
#pragma unroll
    for (int j = 0; j < 4; j++)
#pragma unroll
        for (int p = 0; p < 10; p++) acc[j][p] = make_float2(0.f, 0.f);

    const float* ub = Ul + ((long)xi * 4 + ocg) * (512L * 128);
    const float* vb = V + (long)xi * 512 * TPOS + pos0;

    auto stage_u = [&](int buf, int s) {
        uint32_t ud = smem_u32(&s_u[buf][0]);
        const float4* us = (const float4*)(ub + (long)s * 1024);
        cp_async16(ud + tid * 16, us + tid);
        cp_async16(ud + (tid + 128) * 16, us + tid + 128);
    };
    auto load_v = [&](int s, float* rv) {
#pragma unroll
        for (int k = 0; k < 5; k++) {
            int idx = tid + 128 * k;
            int ici = idx / 80;
            int p   = idx - ici * 80;
            rv[k] = vb[(long)(s * 8 + ici) * TPOS + p];
        }
    };
    auto store_v = [&](int buf, const float* rv) {
#pragma unroll
        for (int k = 0; k < 5; k++) {
            int idx = tid + 128 * k;
            s_v[buf][idx] = make_float2(rv[k], rv[k]);
        }
    };

    // prologue
    {
        float rv[5];
        stage_u(0, 0);
        cp_commit();
        load_v(0, rv);
        store_v(0, rv);
        cp_wait0();
    }
    __syncthreads();

    for (int s = 0; s < 64; s++) {
        const int cur = s & 1;
        float rv[5];
        if (s < 63) {
            stage_u(1 - cur, s + 1);
            cp_commit();
            load_v(s + 1, rv);
        }

#pragma unroll
        for (int i = 0; i < 8; i++) {
            const float4* vp = (const float4*)(&s_v[cur][i * 80 + ps * 10]);
            float2 iv[10];
#pragma unroll
            for (int q = 0; q < 5; q++) {
                float4 f = vp[q];
                iv[2 * q]     = make_float2(f.x, f.y);
                iv[2 * q + 1] = make_float2(f.z, f.w);
            }
            const float4* up = (const float4*)(&s_u[cur][i * 128 + og * 8]);
            float4 w0 = up[0], w1 = up[1];
            float2 wp0 = make_float2(w0.x, w0.y);
            float2 wp1 = make_float2(w0.z, w0.w);
            float2 wp2 = make_float2(w1.x, w1.y);
            float2 wp3 = make_float2(w1.z, w1.w);
#pragma unroll
            for (int p = 0; p < 10; p++) {
                fma2(acc[0][p], wp0, iv[p]);
                fma2(acc[1][p], wp1, iv[p]);
                fma2(acc[2][p], wp2, iv[p]);
                fma2(acc[3][p], wp3, iv[p]);
            }
        }

        if (s < 63) {
            store_v(1 - cur, rv);
            cp_wait0();
        }
        __syncthreads();
    }

#pragma unroll
    for (int j = 0; j < 4; j++) {
        int oc0 = ocg * 128 + og * 8 + 2 * j;
        float* m0 = M + ((long)xi * 512 + oc0) * TPOS + pos0 + ps * 10;
        float* m1 = m0 + TPOS;
#pragma unroll
        for (int p = 0; p < 10; p++) {
            m0[p] = acc[j][p].x;
            m1[p] = acc[j][p].y;
        }
    }
}

// ---------------- fused junction: Y = A^T m A + bias + leaky -> V' = B^T y B ----------------
// one block per (b, ch); smem holds the 40x40 activation channel.
__global__ void __launch_bounds__(128)
wino_junction_k(const float* __restrict__ M, const float* __restrict__ bias,
                float* __restrict__ V)
{
    const int b  = blockIdx.x >> 9;
    const int ch = blockIdx.x & 511;
    __shared__ float yb[1600];
    const float bv = bias[ch];
    const int t = threadIdx.x;

    if (t < NTILE) {
        int ty = t / NT1, tx = t - (t / NT1) * NT1;
        int gt = b * NTILE + t;
        float m[6][6];
#pragma unroll
        for (int xi = 0; xi < XI; xi++)
            m[xi / 6][xi % 6] = M[((long)xi * 512 + ch) * TPOS + gt];
        float s[4][6];
        {
            float col[6], o[4];
#pragma unroll
            for (int c = 0; c < 6; c++) {
#pragma unroll
                for (int r = 0; r < 6; r++) col[r] = m[r][c];
                atcomb(col, o);
#pragma unroll
                for (int r = 0; r < 4; r++) s[r][c] = o[r];
            }
        }
        int o0 = (4 * ty) * 40 + 4 * tx;
#pragma unroll
        for (int r = 0; r < 4; r++) {
            float y[4];
            atcomb(s[r], y);
#pragma unroll
            for (int c = 0; c < 4; c++) {
                float v = y[c] + bv;
                yb[o0 + r * 40 + c] = v > 0.f ? v : 0.1f * v;
            }
        }
    }
    __syncthreads();

    if (t < NTILE) {
        int ty = t / NT1, tx = t - (t / NT1) * NT1;
        int gt = b * NTILE + t;
        float d[6][6];
#pragma unroll
        for (int r = 0; r < 6; r++) {
            int y = 4 * ty - 1 + r;
#pragma unroll
            for (int c = 0; c < 6; c++) {
                int x = 4 * tx - 1 + c;
                d[r][c] = ((unsigned)y < 40u && (unsigned)x < 40u) ? yb[y * 40 + x] : 0.f;
            }
        }
        float z[6][6];
        {
            float col[6], o[6];
#pragma unroll
            for (int c = 0; c < 6; c++) {
#pragma unroll
                for (int r = 0; r < 6; r++) col[r] = d[r][c];
                btcomb(col, o);
#pragma unroll
                for (int r = 0; r < 6; r++) z[r][c] = o[r];
            }
        }
#pragma unroll
        for (int r = 0; r < 6; r++) {
            float o[6];
            btcomb(z[r], o);
#pragma unroll
            for (int c = 0; c < 6; c++)
                V[((long)(r * 6 + c) * 512 + ch) * TPOS + gt] = o[c];
        }
    }
}

// ---------------- output transform (chain ends): Y = A^T m A + bias + leaky ----------------
__global__ void __launch_bounds__(256)
wino_out_k(const float* __restrict__ M, const float* __restrict__ bias,
           float* __restrict__ act)
{
    long i = (long)blockIdx.x * 256 + threadIdx.x;
    if (i >= 512L * TPOS) return;
    int t  = (int)(i % TPOS);
    int oc = (int)(i / TPOS);
    int b  = t / NTILE;
    int tt = t - b * NTILE;
    int ty = tt / NT1;
    int tx = tt - ty * NT1;

    float m[6][6];
#pragma unroll
    for (int xi = 0; xi < XI; xi++)
        m[xi / 6][xi % 6] = M[((long)xi * 512 + oc) * TPOS + t];

    float s[4][6];
    {
        float col[6], o[4];
#pragma unroll
        for (int c = 0; c < 6; c++) {
#pragma unroll
            for (int r = 0; r < 6; r++) col[r] = m[r][c];
            atcomb(col, o);
#pragma unroll
            for (int r = 0; r < 4; r++) s[r][c] = o[r];
        }
    }

    float bv = bias[oc];
    float* ob = act + ((long)b * HEAD + oc) * NPOS + (4 * ty) * 40 + 4 * tx;
#pragma unroll
    for (int r = 0; r < 4; r++) {
        float y[4];
        atcomb(s[r], y);
#pragma unroll
        for (int c = 0; c < 4; c++) {
            float v = y[c] + bv;
            ob[r * 40 + c] = v > 0.f ? v : 0.1f * v;
        }
    }
}

// ---------------- heads, cls half: softmax argmax + 1/sum (runs early on s2) ----------------
__global__ void __launch_bounds__(128)
heads_cls_k(const float* __restrict__ cf,
            const float* __restrict__ clsp_w, const float* __restrict__ clsp_b,
            float* __restrict__ out, float* __restrict__ cprob, int* __restrict__ cls_s)
{
    const int b = blockIdx.y;
    const int p = threadIdx.x & 63;
    const int h = threadIdx.x >> 6;
    const int n = blockIdx.x * 64 + p;
    const int ch0 = h * 256;

    const float* cfb = cf + ((long)b * HEAD + ch0) * NPOS + n;

    float accC[NCLS];
#pragma unroll
    for (int c = 0; c < NCLS; c++) accC[c] = 0.f;

#pragma unroll 4
    for (int ch = 0; ch < 256; ch++) {
        float cv = cfb[(long)ch * NPOS];
#pragma unroll
        for (int c = 0; c < NCLS; c++)
            accC[c] = fmaf(cv, __ldg(&clsp_w[c * HEAD + ch0 + ch]), accC[c]);
    }

    __shared__ float sred[64][NCLS];
    if (h == 1) {
#pragma unroll
        for (int c = 0; c < NCLS; c++) sred[p][c] = accC[c];
    }
    __syncthreads();
    if (h != 0) return;

#pragma unroll
    for (int c = 0; c < NCLS; c++) accC[c] += sred[p][c] + clsp_b[c];

    float mx = accC[0];
    int am = 0;
#pragma unroll
    for (int c = 1; c < NCLS; c++)
        if (accC[c] > mx) { mx = accC[c]; am = c; }
    float s = 0.f;
#pragma unroll
    for (int c = 0; c < NCLS; c++) s += expf(accC[c] - mx);

    const int gi = b * NPOS + n;
    out[OFF_CLS + gi] = (float)am;
    cprob[gi] = 1.f / s;
    cls_s[gi] = am;
}

// ---------------- heads, reg half: obj + boxes + best (after reg chain) ----------------
__global__ void __launch_bounds__(128)
heads_reg_k(const float* __restrict__ rf,
            const float* __restrict__ obj_w, const float* __restrict__ obj_b,
            const float* __restrict__ regp_w, const float* __restrict__ regp_b,
            const float* __restrict__ cprob,
            float* __restrict__ out, float* __restrict__ best_s)
{
    const int b = blockIdx.y;
    const int p = threadIdx.x & 63;
    const int h = threadIdx.x >> 6;
    const int n = blockIdx.x * 64 + p;
    const int ch0 = h * 256;

    const float* rfb = rf + ((long)b * HEAD + ch0) * NPOS + n;

    float accR[4];
    float accO = 0.f;
#pragma unroll
    for (int k = 0; k < 4; k++) accR[k] = 0.f;

#pragma unroll 4
    for (int ch = 0; ch < 256; ch++) {
        float rv = rfb[(long)ch * NPOS];
        accO = fmaf(rv, __ldg(&obj_w[ch0 + ch]), accO);
#pragma unroll
        for (int k = 0; k < 4; k++)
            accR[k] = fmaf(rv, __ldg(&regp_w[k * HEAD + ch0 + ch]), accR[k]);
    }

    __shared__ float sred[64][5];
    if (h == 1) {
#pragma unroll
        for (int k = 0; k < 4; k++) sred[p][k] = accR[k];
        sred[p][4] = accO;
    }
    __syncthreads();
    if (h != 0) return;

#pragma unroll
    for (int k = 0; k < 4; k++) accR[k] += sred[p][k] + regp_b[k];
    accO += sred[p][4] + obj_b[0];

    const int gi = b * NPOS + n;
    float sig_o = 1.f / (1.f + expf(-accO));
    float best  = sig_o * cprob[gi];

    float gx = (float)(n % FMP);
    float gy = (float)(n / FMP);
    float cx = 1.f / (1.f + expf(-accR[0])) + gx;
    float cy = 1.f / (1.f + expf(-accR[1])) + gy;
    float ww = expf(accR[2]);
    float hh = expf(accR[3]);

    float bx1 = (cx - ww * 0.5f) * 32.f / 1280.f;
    float by1 = (cy - hh * 0.5f) * 32.f / 1280.f;
    float bx2 = (cx + ww * 0.5f) * 32.f / 1280.f;
    float by2 = (cy + hh * 0.5f) * 32.f / 1280.f;
    bx1 = fminf(fmaxf(bx1, 0.f), 1.f);
    by1 = fminf(fmaxf(by1, 0.f), 1.f);
    bx2 = fminf(fmaxf(bx2, 0.f), 1.f);
    by2 = fminf(fmaxf(by2, 0.f), 1.f);

    out[gi * 4 + 0] = bx1;
    out[gi * 4 + 1] = by1;
    out[gi * 4 + 2] = bx2;
    out[gi * 4 + 3] = by2;
    out[OFF_BEST + gi] = best;
    out[OFF_KEEP + gi] = 0.f;
    best_s[gi] = best;
}

// ---------------- per-(batch, class) greedy NMS ----------------
__global__ void __launch_bounds__(256)
nms_k(const float* __restrict__ out_boxes,
      float* __restrict__ out_keep,
      const float* __restrict__ best_s, const int* __restrict__ cls_s)
{
    const int b = blockIdx.x / NCLS;
    const int c = blockIdx.x % NCLS;
    const int tid = threadIdx.x;

    __shared__ float sx1[NPOS], sy1[NPOS], sx2[NPOS], sy2[NPOS];
    __shared__ float ssc[NPOS];
    __shared__ int   sidx[NPOS];
    __shared__ unsigned short ord[NPOS];
    __shared__ unsigned char aliveR[NPOS];
    __shared__ int scnt;

    if (tid == 0) scnt = 0;
    __syncthreads();

    for (int n = tid; n < NPOS; n += 256) {
        int gi = b * NPOS + n;
        if (cls_s[gi] == c && best_s[gi] >= CONF_T) {
            int p = atomicAdd(&scnt, 1);
            sidx[p] = n;
            ssc[p]  = best_s[gi];
            const float* bp = out_boxes + (long)gi * 4;
            sx1[p] = bp[0]; sy1[p] = bp[1]; sx2[p] = bp[2]; sy2[p] = bp[3];
        }
    }
    __syncthreads();
    const int cnt = scnt;

    for (int i = tid; i < cnt; i += 256) {
        float si = ssc[i];
        int   ii = sidx[i];
        int rnk = 0;
        for (int j = 0; j < cnt; j++) {
            float sj = ssc[j];
            if (sj > si || (sj == si && sidx[j] < ii)) rnk++;
        }
        ord[rnk] = (unsigned short)i;
        aliveR[rnk] = 1;
    }
    __syncthreads();

    for (int r = 0; r < cnt; r++) {
        __syncthreads();
        if (!aliveR[r]) continue;
        int li = ord[r];
        float bx1 = sx1[li], by1 = sy1[li], bx2 = sx2[li], by2 = sy2[li];
        float ai = (bx2 - bx1) * (by2 - by1);
        for (int rr = r + 1 + tid; rr < cnt; rr += 256) {
            if (!aliveR[rr]) continue;
            int lj = ord[rr];
            float jx1 = sx1[lj], jy1 = sy1[lj], jx2 = sx2[lj], jy2 = sy2[lj];
            float xx1 = fmaxf(bx1, jx1);
            float yy1 = fmaxf(by1, jy1);
            float xx2 = fminf(bx2, jx2);
            float yy2 = fminf(by2, jy2);
            float w2 = fmaxf(1e-28f, xx2 - xx1);
            float h2 = fmaxf(1e-28f, yy2 - yy1);
            float inter = w2 * h2;
            float aj = (jx2 - jx1) * (jy2 - jy1);
            float iou = inter / (ai + aj - inter + 1e-14f);
            if (iou > NMS_T) aliveR[rr] = 0;
        }
    }
    __syncthreads();

    for (int r = tid; r < cnt; r += 256)
        if (aliveR[r])
            out_keep[b * NPOS + sidx[ord[r]]] = 1.f;
}

// ---------------- launch ----------------
extern "C" void kernel_launch(void* const* d_in, const int* in_sizes, int n_in,
                              void* d_out, int out_size)
{
    const float* x      = (const float*)d_in[0];
    const float* cls_w  = (const float*)d_in[1];
    const float* cls_b  = (const float*)d_in[2];
    const float* reg_w  = (const float*)d_in[3];
    const float* reg_b  = (const float*)d_in[4];
    const float* obj_w  = (const float*)d_in[5];
    const float* obj_b  = (const float*)d_in[6];
    const float* clsp_w = (const float*)d_in[7];
    const float* clsp_b = (const float*)d_in[8];
    const float* regp_w = (const float*)d_in[9];
    const float* regp_b = (const float*)d_in[10];
    float* out = (float*)d_out;

    void *pB, *pC, *pBest, *pCpr, *pCls, *pU, *pVx, *pV0, *pM0, *pV1, *pM1;
    cudaGetSymbolAddress(&pB, g_bufB);
    cudaGetSymbolAddress(&pC, g_bufC);
    cudaGetSymbolAddress(&pBest, g_best);
    cudaGetSymbolAddress(&pCpr, g_cprob);
    cudaGetSymbolAddress(&pCls, g_clsi);
    cudaGetSymbolAddress(&pU, g_U);
    cudaGetSymbolAddress(&pVx, g_Vx);
    cudaGetSymbolAddress(&pV0, g_V0);
    cudaGetSymbolAddress(&pM0, g_M0);
    cudaGetSymbolAddress(&pV1, g_V1);
    cudaGetSymbolAddress(&pM1, g_M1);
    float* bufB  = (float*)pB;
    float* bufC  = (float*)pC;
    float* bestp = (float*)pBest;
    float* cprob = (float*)pCpr;
    int*   clsp  = (int*)pCls;
    float* U     = (float*)pU;
    float* Vx    = (float*)pVx;
    float* V0    = (float*)pV0;
    float* M0    = (float*)pM0;
    float* V1    = (float*)pV1;
    float* M1    = (float*)pM1;

    static cudaStream_t s2 = 0;
    static cudaEvent_t  evFork = 0, evWT = 0, evVx = 0, evCls = 0;
    if (!s2) {
        cudaStreamCreateWithFlags(&s2, cudaStreamNonBlocking);
        cudaEventCreateWithFlags(&evFork, cudaEventDisableTiming);
        cudaEventCreateWithFlags(&evWT, cudaEventDisableTiming);
        cudaEventCreateWithFlags(&evVx, cudaEventDisableTiming);
        cudaEventCreateWithFlags(&evCls, cudaEventDisableTiming);
    }

    const int TGRID = (int)((512L * TPOS + 255) / 256);   // 1600
    const int JGRID = Bs * HEAD;                          // 4096
    dim3 ggrid(TPOS / 80, 4, XI);                          // (10, 4, 36)
    dim3 hgrid(TPOS / 64 * 8 / Bs, Bs);                    // (25 pos-blocks? no) -- computed below

    // fork s2
    cudaEventRecord(evFork, 0);
    cudaStreamWaitEvent(s2, evFork, 0);

    // weight transform on s2, input transform on default (parallel)
    {
        long total = 6L * 512 * 512;
        int  grid  = (int)((total + 255) / 256);
        wino_wt_k<<<grid, 256, 0, s2>>>(cls_w, reg_w, U);
    }
    cudaEventRecord(evWT, s2);
    wino_in_k<<<TGRID, 256>>>(x, Vx);
    cudaEventRecord(evVx, 0);

    // GEMMs need U: default stream waits for wt; s2 waits for Vx
    cudaStreamWaitEvent(0, evWT, 0);
    cudaStreamWaitEvent(s2, evVx, 0);

    // cls branch (s2): Vx -> M1 -> junction -> M1 -> bufB -> heads_cls
    wino_gemm_k<<<ggrid, 128, 0, s2>>>(Vx, U + 0L * U_L, M1);
    wino_junction_k<<<JGRID, 128, 0, s2>>>(M1, cls_b, V1);
    wino_gemm_k<<<ggrid, 128, 0, s2>>>(V1, U + 1L * U_L, M1);
    wino_out_k<<<TGRID, 256, 0, s2>>>(M1, cls_b + HEAD, bufB);
    heads_cls_k<<<dim3(25, Bs), 128, 0, s2>>>(bufB, clsp_w, clsp_b, out, cprob, clsp);
    cudaEventRecord(evCls, s2);

    // reg branch (default): Vx -> M0 -> junction -> ... -> bufC
    wino_gemm_k<<<ggrid, 128>>>(Vx, U + 2L * U_L, M0);
    wino_junction_k<<<JGRID, 128>>>(M0, reg_b, V0);
    wino_gemm_k<<<ggrid, 128>>>(V0, U + 3L * U_L, M0);
    wino_junction_k<<<JGRID, 128>>>(M0, reg_b + HEAD, V0);
    wino_gemm_k<<<ggrid, 128>>>(V0, U + 4L * U_L, M0);
    wino_junction_k<<<JGRID, 128>>>(M0, reg_b + 2 * HEAD, V0);
    wino_gemm_k<<<ggrid, 128>>>(V0, U + 5L * U_L, M0);
    wino_out_k<<<TGRID, 256>>>(M0, reg_b + 3 * HEAD, bufC);

    // join: heads_reg needs cprob (from s2) + bufC
    cudaStreamWaitEvent(0, evCls, 0);
    heads_reg_k<<<dim3(25, Bs), 128>>>(bufC, obj_w, obj_b, regp_w, regp_b,
                                       cprob, out, bestp);

    nms_k<<<Bs * NCLS, 256>>>(out, out + OFF_KEEP, bestp, clsp);
}